// round 3
// baseline (speedup 1.0000x reference)
#include <cuda_runtime.h>
#include <cuda_bf16.h>
#include <math.h>

// ---------------- problem constants ----------------
#define PB 256
#define PN 128
#define PD 768
#define PE 3
#define PS 44
#define PES 132
#define PH 1024
#define PMAXS 88
#define PM_TOK (PB*PN)
#define PM_FFN (PB*PS)

// ---------------- scratch (device globals) ----------------
__device__ float g_slot_input[PB * 769];
__device__ float g_slot_bias [PB * PD];
__device__ float g_img_n     [PM_TOK * PD];
__device__ float g_dot       [PM_TOK];
__device__ float g_mu_cat    [PD * PES];
__device__ float g_logits    [PM_TOK * PES];
__device__ float g_dispatch  [PM_TOK * PES];
__device__ float g_combine   [PM_TOK * PES];
__device__ float g_slot_in   [PB * PES * PD];
__device__ float g_hbuf      [PB * PES * PH];
__device__ float g_slot_out  [PB * PES * PD];
__device__ float g_cls_h     [PB * 4 * PD];

__device__ __forceinline__ float gelu_exact(float x) {
    return 0.5f * x * (1.0f + erff(x * 0.70710678118654752440f));
}
__device__ __forceinline__ unsigned f2tf(float x) {
    unsigned u; asm("cvt.rna.tf32.f32 %0, %1;" : "=r"(u) : "f"(x)); return u;
}
// split x into hi (tf32) and lo (tf32 of residual)
__device__ __forceinline__ void split_tf(float x, unsigned& hi, unsigned& lo) {
    hi = f2tf(x);
    lo = f2tf(x - __uint_as_float(hi));
}
__device__ __forceinline__ void mma8(float* c, const unsigned* a, const unsigned* b) {
    asm volatile(
      "mma.sync.aligned.m16n8k8.row.col.f32.tf32.tf32.f32 "
      "{%0,%1,%2,%3}, {%4,%5,%6,%7}, {%8,%9}, {%0,%1,%2,%3};"
      : "+f"(c[0]), "+f"(c[1]), "+f"(c[2]), "+f"(c[3])
      : "r"(a[0]), "r"(a[1]), "r"(a[2]), "r"(a[3]), "r"(b[0]), "r"(b[1]));
}

// ---------------- 3xTF32 tensor-core GEMM ----------------
// C[M,N] = A[M,K] @ B[K,N] row-major; batch via blockIdx.z with strides.
// TRANS_A: A stored (K,M). MAP_ROWS: row m -> (m/44)*132 + z*44 + m%44 on A & C.
#define EP_STORE     0
#define EP_BIAS      1
#define EP_BIAS_GELU 2
#define EP_LOGITS    3

template<bool GUARD, bool TRANS_A, bool MAP_ROWS, int EP>
__global__ __launch_bounds__(256)
void tgemm(const float* __restrict__ A, const float* __restrict__ B,
           float* __restrict__ C,
           int M, int N, int K, int lda, int ldb, int ldc,
           long long sA, long long sB, long long sC,
           const float* __restrict__ v1, const float* __restrict__ v2,
           const float* __restrict__ scale_ptr, int biasStride)
{
    const int z = blockIdx.z;
    const float* Ab = A + (long long)z * sA;
    const float* Bb = B + (long long)z * sB;
    float*       Cb = C + (long long)z * sC;

    // fragment-permuted smem, hi/lo planes:
    // As[kblock][mtile16][(r*4+c)*4+q]  q = {(r,c),(r+8,c),(r,c+4),(r+8,c+4)}
    // Bs[kblock][ntile8 ][(n*4+c)*2+pr] pr = {k=c, k=c+4}
    __shared__ __align__(16) unsigned AsH[2][8][128];
    __shared__ __align__(16) unsigned AsL[2][8][128];
    __shared__ __align__(16) unsigned BsH[2][16][64];
    __shared__ __align__(16) unsigned BsL[2][16][64];

    const int tid  = threadIdx.x;
    const int lane = tid & 31;
    const int wid  = tid >> 5;
    const int wm   = wid & 1;     // 2 warps in M (64 each)
    const int wn   = wid >> 1;    // 4 warps in N (32 each)
    const int m0 = blockIdx.x * 128;
    const int n0 = blockIdx.y * 128;

    float acc[4][4][4];
    #pragma unroll
    for (int i = 0; i < 4; i++)
        #pragma unroll
        for (int j = 0; j < 4; j++)
            #pragma unroll
            for (int q = 0; q < 4; q++) acc[i][j][q] = 0.f;

    // A loader (non-trans): thread -> (row 0..127, half-k 0/8)
    const int arow  = tid >> 1;
    const int ahalf = (tid & 1) * 8;
    // trans-A / B loader: thread -> (k 0..15, 8 consecutive cols)
    const int t_k = tid >> 4;
    const int t_c = (tid & 15) * 8;

    long long a_off = 0;
    bool a_ok = true;
    if (!TRANS_A) {
        const int gm = m0 + arow;
        a_ok = (gm < M);
        int amr = gm;
        if (MAP_ROWS) amr = (gm / 44) * PES + z * PS + (gm % 44);
        a_off = (long long)amr * lda;
    }

    const int nk = (K + 15) >> 4;
    for (int kt = 0; kt < nk; kt++) {
        const int k0 = kt << 4;
        float av[8], bv[8];
        // ---- global loads ----
        if (!TRANS_A) {
            if (!GUARD) {
                const float4 u0 = *reinterpret_cast<const float4*>(Ab + a_off + k0 + ahalf);
                const float4 u1 = *reinterpret_cast<const float4*>(Ab + a_off + k0 + ahalf + 4);
                av[0]=u0.x; av[1]=u0.y; av[2]=u0.z; av[3]=u0.w;
                av[4]=u1.x; av[5]=u1.y; av[6]=u1.z; av[7]=u1.w;
            } else {
                #pragma unroll
                for (int j = 0; j < 8; j++) {
                    const int k = k0 + ahalf + j;
                    av[j] = (a_ok && k < K) ? Ab[a_off + k] : 0.f;
                }
            }
        } else {
            const int gk = k0 + t_k;
            #pragma unroll
            for (int j = 0; j < 8; j++) {
                const int gm = m0 + t_c + j;
                av[j] = (gk < K && gm < M) ? Ab[(long long)gk * lda + gm] : 0.f;
            }
        }
        {
            const int gk = k0 + t_k;
            if (!GUARD) {
                const float4 u0 = *reinterpret_cast<const float4*>(Bb + (long long)gk * ldb + n0 + t_c);
                const float4 u1 = *reinterpret_cast<const float4*>(Bb + (long long)gk * ldb + n0 + t_c + 4);
                bv[0]=u0.x; bv[1]=u0.y; bv[2]=u0.z; bv[3]=u0.w;
                bv[4]=u1.x; bv[5]=u1.y; bv[6]=u1.z; bv[7]=u1.w;
            } else {
                #pragma unroll
                for (int j = 0; j < 8; j++) {
                    const int gn = n0 + t_c + j;
                    bv[j] = (gk < K && gn < N) ? Bb[(long long)gk * ldb + gn] : 0.f;
                }
            }
        }
        __syncthreads();   // previous compute finished
        // ---- scatter to fragment layout (hi/lo) ----
        #pragma unroll
        for (int j = 0; j < 8; j++) {
            int kl, rowl;
            if (!TRANS_A) { kl = ahalf + j; rowl = arow; }
            else          { kl = t_k;       rowl = t_c + j; }
            const int kb = kl >> 3, kk = kl & 7;
            const int mt = rowl >> 4, rq = rowl & 15;
            const int idx = ((rq & 7) * 4 + (kk & 3)) * 4 + ((kk >> 2) * 2 + (rq >> 3));
            unsigned h, l;
            split_tf(av[j], h, l);
            AsH[kb][mt][idx] = h;
            AsL[kb][mt][idx] = l;
        }
        {
            const int kb = t_k >> 3, kk = t_k & 7;
            const int c = kk & 3, pr = kk >> 2;
            #pragma unroll
            for (int j = 0; j < 8; j++) {
                const int nidx = t_c + j;
                const int idx = ((nidx & 7) * 4 + c) * 2 + pr;
                unsigned h, l;
                split_tf(bv[j], h, l);
                BsH[kb][nidx >> 3][idx] = h;
                BsL[kb][nidx >> 3][idx] = l;
            }
        }
        __syncthreads();
        // ---- compute: hi*hi + hi*lo + lo*hi ----
        #pragma unroll
        for (int kb = 0; kb < 2; kb++) {
            uint4 afH[4], afL[4];
            uint2 bfH[4], bfL[4];
            #pragma unroll
            for (int mt = 0; mt < 4; mt++) {
                afH[mt] = *reinterpret_cast<const uint4*>(&AsH[kb][wm * 4 + mt][lane * 4]);
                afL[mt] = *reinterpret_cast<const uint4*>(&AsL[kb][wm * 4 + mt][lane * 4]);
            }
            #pragma unroll
            for (int nt = 0; nt < 4; nt++) {
                bfH[nt] = *reinterpret_cast<const uint2*>(&BsH[kb][wn * 4 + nt][lane * 2]);
                bfL[nt] = *reinterpret_cast<const uint2*>(&BsL[kb][wn * 4 + nt][lane * 2]);
            }
            #pragma unroll
            for (int mt = 0; mt < 4; mt++)
                #pragma unroll
                for (int nt = 0; nt < 4; nt++) {
                    float* c = acc[mt][nt];
                    mma8(c, reinterpret_cast<const unsigned*>(&afL[mt]),
                            reinterpret_cast<const unsigned*>(&bfH[nt]));
                    mma8(c, reinterpret_cast<const unsigned*>(&afH[mt]),
                            reinterpret_cast<const unsigned*>(&bfL[nt]));
                    mma8(c, reinterpret_cast<const unsigned*>(&afH[mt]),
                            reinterpret_cast<const unsigned*>(&bfH[nt]));
                }
        }
    }
    __syncthreads();

    // ---- epilogue ----
    const int lr = lane >> 2;
    const int lc = (lane & 3) * 2;
    #pragma unroll
    for (int mt = 0; mt < 4; mt++) {
        #pragma unroll
        for (int h = 0; h < 2; h++) {
            const int gm = m0 + wm * 64 + mt * 16 + lr + h * 8;
            if (GUARD && gm >= M) continue;
            int rr = gm;
            if (MAP_ROWS) rr = (gm / 44) * PES + z * PS + (gm % 44);
            float dd = 0.f; int sel = 0;
            if (EP == EP_LOGITS) {
                const float w = v1[gm];
                dd = v2[gm];
                sel = (w > 0.7f) ? 0 : ((w >= 0.3f) ? 1 : 2);
            }
            float* crow = Cb + (long long)rr * ldc;
            #pragma unroll
            for (int nt = 0; nt < 4; nt++) {
                #pragma unroll
                for (int jj = 0; jj < 2; jj++) {
                    const int gn = n0 + wn * 32 + nt * 8 + lc + jj;
                    if (GUARD && gn >= N) continue;
                    float v = acc[mt][nt][h * 2 + jj];
                    if (EP == EP_BIAS) {
                        v += v1[z * biasStride + gn];
                    } else if (EP == EP_BIAS_GELU) {
                        v = gelu_exact(v + v1[z * biasStride + gn]);
                    } else if (EP == EP_LOGITS) {
                        v = ((gn / PS) == sel) ? (scale_ptr[0] * (v + dd)) : 0.f;
                    }
                    crow[gn] = v;
                }
            }
        }
    }
}

// ---------------- mu rearrange ----------------
__global__ void k_prep_mu(const float* __restrict__ mu, float* __restrict__ mu_cat) {
    int idx = blockIdx.x * blockDim.x + threadIdx.x;
    if (idx >= PD * PES) return;
    int d = idx / PES, j = idx % PES;
    int e = j / PS, s = j % PS;
    mu_cat[idx] = mu[((long long)e * PD + d) * PMAXS + s];
}

// ---------------- slot_input = [cls, mean(attn)] ----------------
__global__ void k_build_slotinput(const float* __restrict__ x,
                                  const float* __restrict__ attn,
                                  float* __restrict__ si) {
    int b = blockIdx.x;
    int t = threadIdx.x;
    __shared__ float red[8];
    float s = (t < PN) ? attn[b * PN + t] : 0.f;
    for (int o = 16; o; o >>= 1) s += __shfl_xor_sync(~0u, s, o);
    if ((t & 31) == 0) red[t >> 5] = s;
    __syncthreads();
    const float* cls = x + (long long)b * 129 * PD;
    float* o = si + (long long)b * 769;
    for (int d = t; d < PD; d += 256) o[d] = cls[d];
    if (t == 0) {
        float m = 0.f;
        #pragma unroll
        for (int i = 0; i < 8; i++) m += red[i];
        o[PD] = m * (1.f / (float)PN);
    }
}

// ---------------- LayerNorm + dot ----------------
__global__ void k_ln_dot(const float* __restrict__ x,
                         const float* __restrict__ gamma,
                         const float* __restrict__ beta,
                         const float* __restrict__ slot_bias,
                         float* __restrict__ img_n,
                         float* __restrict__ dot) {
    const int m = blockIdx.x;
    const int b = m >> 7;
    const int n = m & 127;
    const float* row = x + ((long long)b * 129 + 1 + n) * PD;
    const int t = threadIdx.x;
    const int w = t >> 5, l = t & 31;
    __shared__ float rs[8], rq[8];

    float v[3], s = 0.f, sq = 0.f;
    #pragma unroll
    for (int i = 0; i < 3; i++) {
        v[i] = row[t + i * 256];
        s += v[i];
        sq += v[i] * v[i];
    }
    for (int o = 16; o; o >>= 1) {
        s  += __shfl_xor_sync(~0u, s, o);
        sq += __shfl_xor_sync(~0u, sq, o);
    }
    if (l == 0) { rs[w] = s; rq[w] = sq; }
    __syncthreads();
    float ts = 0.f, tq = 0.f;
    #pragma unroll
    for (int i = 0; i < 8; i++) { ts += rs[i]; tq += rq[i]; }
    const float mean = ts * (1.f / (float)PD);
    const float var  = tq * (1.f / (float)PD) - mean * mean;
    const float inv  = rsqrtf(var + 1e-5f);
    __syncthreads();

    const float* sb = slot_bias + (long long)b * PD;
    float* orow = img_n + (long long)m * PD;
    float dp = 0.f;
    #pragma unroll
    for (int i = 0; i < 3; i++) {
        const int d = t + i * 256;
        const float y = (v[i] - mean) * inv * gamma[d] + beta[d];
        orow[d] = y;
        dp += y * sb[d];
    }
    for (int o = 16; o; o >>= 1) dp += __shfl_xor_sync(~0u, dp, o);
    if (l == 0) rs[w] = dp;
    __syncthreads();
    if (t == 0) {
        float d2 = 0.f;
        #pragma unroll
        for (int i = 0; i < 8; i++) d2 += rs[i];
        dot[m] = d2;
    }
}

// ---------------- dispatch softmax (over tokens) ----------------
__global__ void k_dispatch(const float* __restrict__ logits, float* __restrict__ disp) {
    const int be = blockIdx.x;
    const int b = be / PE, e = be % PE;
    __shared__ float tile[PN][PS];
    __shared__ float csum[PS];
    const int t = threadIdx.x;
    const float* base = logits + (long long)b * PN * PES + e * PS;
    for (int idx = t; idx < PN * PS; idx += 256) {
        const int n = idx / PS, j = idx % PS;
        tile[n][j] = base[(long long)n * PES + j];
    }
    __syncthreads();
    if (t < PS) {
        float mx = -1e30f;
        for (int n = 0; n < PN; n++) mx = fmaxf(mx, tile[n][t]);
        float sm = 0.f;
        for (int n = 0; n < PN; n++) {
            const float ev = expf(tile[n][t] - mx);
            tile[n][t] = ev;
            sm += ev;
        }
        csum[t] = sm;
    }
    __syncthreads();
    float* ob = disp + (long long)b * PN * PES + e * PS;
    for (int idx = t; idx < PN * PS; idx += 256) {
        const int n = idx / PS, j = idx % PS;
        ob[(long long)n * PES + j] = tile[n][j] / csum[j];
    }
}

// ---------------- combine softmax (over 132 slots) ----------------
__global__ void k_combine(const float* __restrict__ logits, float* __restrict__ comb) {
    const int row = blockIdx.x * 8 + (threadIdx.x >> 5);
    const int l = threadIdx.x & 31;
    if (row >= PM_TOK) return;
    const float* r = logits + (long long)row * PES;
    float vals[5], mx = -1e30f;
    #pragma unroll
    for (int i = 0; i < 5; i++) {
        const int j = l + i * 32;
        vals[i] = (j < PES) ? r[j] : -1e30f;
        mx = fmaxf(mx, vals[i]);
    }
    for (int o = 16; o; o >>= 1) mx = fmaxf(mx, __shfl_xor_sync(~0u, mx, o));
    float s = 0.f;
    #pragma unroll
    for (int i = 0; i < 5; i++) {
        const int j = l + i * 32;
        if (j < PES) { vals[i] = expf(vals[i] - mx); s += vals[i]; }
    }
    for (int o = 16; o; o >>= 1) s += __shfl_xor_sync(~0u, s, o);
    const float inv = 1.f / s;
    float* o = comb + (long long)row * PES;
    #pragma unroll
    for (int i = 0; i < 5; i++) {
        const int j = l + i * 32;
        if (j < PES) o[j] = vals[i] * inv;
    }
}

// ---------------- launch ----------------
extern "C" void kernel_launch(void* const* d_in, const int* in_sizes, int n_in,
                              void* d_out, int out_size) {
    const float* x      = (const float*)d_in[0];
    const float* attn   = (const float*)d_in[1];
    const float* gamma  = (const float*)d_in[2];
    const float* beta   = (const float*)d_in[3];
    const float* vsg_w  = (const float*)d_in[4];
    const float* vsg_b  = (const float*)d_in[5];
    const float* mu     = (const float*)d_in[6];
    const float* scale  = (const float*)d_in[7];
    const float* w1     = (const float*)d_in[8];
    const float* b1     = (const float*)d_in[9];
    const float* w2     = (const float*)d_in[10];
    const float* b2     = (const float*)d_in[11];
    const float* cw1    = (const float*)d_in[12];
    const float* cb1    = (const float*)d_in[13];
    const float* cw2    = (const float*)d_in[14];
    const float* cb2    = (const float*)d_in[15];
    float* out = (float*)d_out;

    float *p_si, *p_sb, *p_imgn, *p_dot, *p_mu, *p_log, *p_disp, *p_comb;
    float *p_sin, *p_h, *p_sout, *p_clsh;
    cudaGetSymbolAddress((void**)&p_si,   g_slot_input);
    cudaGetSymbolAddress((void**)&p_sb,   g_slot_bias);
    cudaGetSymbolAddress((void**)&p_imgn, g_img_n);
    cudaGetSymbolAddress((void**)&p_dot,  g_dot);
    cudaGetSymbolAddress((void**)&p_mu,   g_mu_cat);
    cudaGetSymbolAddress((void**)&p_log,  g_logits);
    cudaGetSymbolAddress((void**)&p_disp, g_dispatch);
    cudaGetSymbolAddress((void**)&p_comb, g_combine);
    cudaGetSymbolAddress((void**)&p_sin,  g_slot_in);
    cudaGetSymbolAddress((void**)&p_h,    g_hbuf);
    cudaGetSymbolAddress((void**)&p_sout, g_slot_out);
    cudaGetSymbolAddress((void**)&p_clsh, g_cls_h);

    // 1. mu -> (768,132)
    k_prep_mu<<<(PD * PES + 255) / 256, 256>>>(mu, p_mu);
    // 2. slot_input
    k_build_slotinput<<<PB, 256>>>(x, attn, p_si);
    // 3. slot_bias = slot_input @ vsg_w + vsg_b   (256,768,K=769)
    tgemm<true, false, false, EP_BIAS><<<dim3(2, 6, 1), 256>>>(
        p_si, vsg_w, p_sb, PB, PD, 769, 769, PD, PD,
        0, 0, 0, vsg_b, nullptr, nullptr, 0);
    // 4. LayerNorm + dot
    k_ln_dot<<<PM_TOK, 256>>>(x, gamma, beta, p_sb, p_imgn, p_dot);
    // 5. logits (32768,132,K=768)
    tgemm<true, false, false, EP_LOGITS><<<dim3(PM_TOK / 128, 2, 1), 256>>>(
        p_imgn, p_mu, p_log, PM_TOK, PES, PD, PD, PES, PES,
        0, 0, 0, attn, p_dot, scale, 0);
    // 6/7. softmaxes
    k_dispatch<<<PB * PE, 256>>>(p_log, p_disp);
    k_combine<<<PM_TOK / 8, 256>>>(p_log, p_comb);
    // 8. slot_in[b] = dispatch[b]^T @ img[b]   (132,768,K=128) batched
    tgemm<true, true, false, EP_STORE><<<dim3(2, 6, PB), 256>>>(
        p_disp, x + PD, p_sin, PES, PD, PN, PES, PD, PD,
        (long long)PN * PES, (long long)129 * PD, (long long)PES * PD,
        nullptr, nullptr, nullptr, 0);
    // 9. FFN1 (11264,1024,K=768) per expert
    tgemm<false, false, true, EP_BIAS_GELU><<<dim3(PM_FFN / 128, PH / 128, PE), 256>>>(
        p_sin, w1, p_h, PM_FFN, PH, PD, PD, PH, PH,
        0, (long long)PD * PH, 0, b1, nullptr, nullptr, PH);
    // 10. FFN2 (11264,768,K=1024) per expert
    tgemm<false, false, true, EP_BIAS><<<dim3(PM_FFN / 128, PD / 128, PE), 256>>>(
        p_h, w2, p_sout, PM_FFN, PD, PH, PH, PD, PD,
        0, (long long)PH * PD, 0, b2, nullptr, nullptr, PD);
    // 11. img_out[b] = combine[b] @ slot_out[b]  (128,768,K=132) batched
    tgemm<true, false, false, EP_STORE><<<dim3(1, 6, PB), 256>>>(
        p_comb, p_sout, out + PD, PN, PD, PES, PES, PD, PD,
        (long long)PN * PES, (long long)PES * PD, (long long)129 * PD,
        nullptr, nullptr, nullptr, 0);
    // 12. cls1 (256,3072,K=768)
    tgemm<false, false, false, EP_BIAS_GELU><<<dim3(2, 24, 1), 256>>>(
        x, cw1, p_clsh, PB, 4 * PD, PD, 129 * PD, 4 * PD, 4 * PD,
        0, 0, 0, cb1, nullptr, nullptr, 0);
    // 13. cls2 (256,768,K=3072) -> out row 0
    tgemm<false, false, false, EP_BIAS><<<dim3(2, 6, 1), 256>>>(
        p_clsh, cw2, out, PB, PD, 4 * PD, 4 * PD, PD, 129 * PD,
        0, 0, 0, cb2, nullptr, nullptr, 0);
}

// round 5
// speedup vs baseline: 1.5822x; 1.5822x over previous
#include <cuda_runtime.h>
#include <cuda_bf16.h>
#include <math.h>
#include <cstdint>

// ---------------- problem constants ----------------
#define PB 256
#define PN 128
#define PD 768
#define PE 3
#define PS 44
#define PES 132
#define PH 1024
#define PMAXS 88
#define PM_TOK (PB*PN)
#define PM_FFN (PB*PS)

// ---------------- scratch (device globals) ----------------
__device__ float g_slot_input[PB * 769];
__device__ float g_slot_bias [PB * PD];
__device__ float g_img_n     [PM_TOK * PD];
__device__ float g_dot       [PM_TOK];
__device__ float g_mu_cat    [PD * PES];
__device__ float g_logits    [PM_TOK * PES];
__device__ float g_dispatch  [PM_TOK * PES];
__device__ float g_combine   [PM_TOK * PES];
__device__ float g_slot_in   [PB * PES * PD];
__device__ float g_hbuf      [PB * PES * PH];
__device__ float g_slot_out  [PB * PES * PD];
__device__ float g_cls_h     [PB * 4 * PD];

// ---------------- helpers ----------------
__device__ __forceinline__ float gelu_exact(float x) {
    return 0.5f * x * (1.0f + erff(x * 0.70710678118654752440f));
}
// packed fp32x2 FMA (sm_100+ family SIMD fp32 — 2x FFMA throughput)
__device__ __forceinline__ unsigned long long bcast2(float x) {
    unsigned long long r;
    asm("mov.b64 %0, {%1, %1};" : "=l"(r) : "r"(__float_as_uint(x)));
    return r;
}
__device__ __forceinline__ void ffma2(unsigned long long& c,
                                      unsigned long long a,
                                      unsigned long long b) {
    asm("fma.rn.f32x2 %0, %1, %2, %0;" : "+l"(c) : "l"(a), "l"(b));
}

// ---------------- FFMA2 tiled SGEMM ----------------
// C[M,N] = A[M,K] @ B[K,N] row-major; batch via blockIdx.z strides.
// TRANS_A: A stored (K,M). MAP_ROWS: row m -> (m/44)*132 + z*44 + m%44 on A & C.
// GUARD: enables all runtime edge guards (M rows, N cols, K tail).
#define EP_STORE     0
#define EP_BIAS      1
#define EP_BIAS_GELU 2
#define EP_LOGITS    3

// tile: BM=128, BN=128, BK=16; 256 threads; thread tile 8 rows x 8 cols.
template<bool GUARD, bool TRANS_A, bool MAP_ROWS, int EP>
__global__ __launch_bounds__(256)
void fgemm2(const float* __restrict__ A, const float* __restrict__ B,
            float* __restrict__ C,
            int M, int N, int K, int lda, int ldb, int ldc,
            long long sA, long long sB, long long sC,
            const float* __restrict__ v1, const float* __restrict__ v2,
            const float* __restrict__ scale_ptr, int biasStride)
{
    const int z = blockIdx.z;
    const float* Ab = A + (long long)z * sA;
    const float* Bb = B + (long long)z * sB;
    float*       Cb = C + (long long)z * sC;

    __shared__ __align__(16) float As[16][128];
    __shared__ __align__(16) float Bs[16][128];

    const int tid = threadIdx.x;          // 256
    const int tx = tid & 15;              // col group
    const int ty = tid >> 4;              // row group
    const int m0 = blockIdx.x * 128;
    const int n0 = blockIdx.y * 128;

    unsigned long long acc[8][4];
    #pragma unroll
    for (int i = 0; i < 8; i++)
        #pragma unroll
        for (int p = 0; p < 4; p++) acc[i][p] = 0ull;

    // A loader (non-trans): thread -> row tid>>1, k-half (tid&1)*8
    const int a_r  = tid >> 1;
    const int a_c8 = (tid & 1) * 8;
    // trans-A / B loader: thread -> k = tid>>4, 8 consecutive cols
    const int t_k = tid >> 4;
    const int t_c = (tid & 15) * 8;

    long long a_off = 0;
    bool a_ok = true;
    if (!TRANS_A) {
        const int gm = m0 + a_r;
        a_ok = !GUARD || (gm < M);
        int rr = gm;
        if (MAP_ROWS) rr = (gm / 44) * PES + z * PS + (gm % 44);
        a_off = (long long)rr * lda;
    }
    const bool bColsOk = !GUARD || (n0 + 128 <= N);

    const int nk = (K + 15) >> 4;
    for (int kt = 0; kt < nk; kt++) {
        const int k0 = kt << 4;
        const bool kfull = !GUARD || (k0 + 16 <= K);
        // ---- load A tile -> As[k][m] ----
        if (!TRANS_A) {
            const bool fast = (!GUARD) || (a_ok && kfull && ((a_off & 3) == 0));
            if (fast) {
                const float4 u0 = *reinterpret_cast<const float4*>(Ab + a_off + k0 + a_c8);
                const float4 u1 = *reinterpret_cast<const float4*>(Ab + a_off + k0 + a_c8 + 4);
                As[a_c8 + 0][a_r] = u0.x; As[a_c8 + 1][a_r] = u0.y;
                As[a_c8 + 2][a_r] = u0.z; As[a_c8 + 3][a_r] = u0.w;
                As[a_c8 + 4][a_r] = u1.x; As[a_c8 + 5][a_r] = u1.y;
                As[a_c8 + 6][a_r] = u1.z; As[a_c8 + 7][a_r] = u1.w;
            } else {
                #pragma unroll
                for (int j = 0; j < 8; j++) {
                    const int k = k0 + a_c8 + j;
                    As[a_c8 + j][a_r] = (a_ok && k < K) ? Ab[a_off + k] : 0.f;
                }
            }
        } else {
            const int gk = k0 + t_k;
            const bool fast = (!GUARD) || ((gk < K) && (m0 + t_c + 8 <= M));
            if (fast) {
                const long long ro = (long long)gk * lda + m0 + t_c;
                if ((ro & 3) == 0) {
                    *reinterpret_cast<float4*>(&As[t_k][t_c])     = *reinterpret_cast<const float4*>(Ab + ro);
                    *reinterpret_cast<float4*>(&As[t_k][t_c + 4]) = *reinterpret_cast<const float4*>(Ab + ro + 4);
                } else {
                    #pragma unroll
                    for (int j = 0; j < 8; j++) As[t_k][t_c + j] = Ab[ro + j];
                }
            } else {
                #pragma unroll
                for (int j = 0; j < 8; j++) {
                    const int gm = m0 + t_c + j;
                    As[t_k][t_c + j] = (gk < K && gm < M) ? Ab[(long long)gk * lda + gm] : 0.f;
                }
            }
        }
        // ---- load B tile -> Bs[k][n] ----
        {
            const int gk = k0 + t_k;
            const bool fast = (!GUARD) || ((gk < K) && bColsOk);
            if (fast) {
                const long long ro = (long long)gk * ldb + n0 + t_c;
                if ((ro & 3) == 0) {
                    *reinterpret_cast<float4*>(&Bs[t_k][t_c])     = *reinterpret_cast<const float4*>(Bb + ro);
                    *reinterpret_cast<float4*>(&Bs[t_k][t_c + 4]) = *reinterpret_cast<const float4*>(Bb + ro + 4);
                } else {
                    #pragma unroll
                    for (int j = 0; j < 8; j++) Bs[t_k][t_c + j] = Bb[ro + j];
                }
            } else {
                #pragma unroll
                for (int j = 0; j < 8; j++) {
                    const int gn = n0 + t_c + j;
                    Bs[t_k][t_c + j] = (gk < K && gn < N) ? Bb[(long long)gk * ldb + gn] : 0.f;
                }
            }
        }
        __syncthreads();
        // ---- compute: 8 rows x 8 cols per thread via fma.f32x2 ----
        #pragma unroll
        for (int k = 0; k < 16; k++) {
            const float4 a0 = *reinterpret_cast<const float4*>(&As[k][ty * 8]);
            const float4 a1 = *reinterpret_cast<const float4*>(&As[k][ty * 8 + 4]);
            const unsigned long long* brow = reinterpret_cast<const unsigned long long*>(&Bs[k][0]);
            const ulonglong2 bl = *reinterpret_cast<const ulonglong2*>(&brow[tx * 2]);
            const ulonglong2 bh = *reinterpret_cast<const ulonglong2*>(&brow[32 + tx * 2]);
            const float av[8] = {a0.x, a0.y, a0.z, a0.w, a1.x, a1.y, a1.z, a1.w};
            #pragma unroll
            for (int i = 0; i < 8; i++) {
                const unsigned long long ap = bcast2(av[i]);
                ffma2(acc[i][0], ap, bl.x);
                ffma2(acc[i][1], ap, bl.y);
                ffma2(acc[i][2], ap, bh.x);
                ffma2(acc[i][3], ap, bh.y);
            }
        }
        __syncthreads();
    }

    // ---- epilogue ----
    #pragma unroll
    for (int i = 0; i < 8; i++) {
        const int gm = m0 + ty * 8 + i;
        if (GUARD && gm >= M) continue;
        int rr = gm;
        if (MAP_ROWS) rr = (gm / 44) * PES + z * PS + (gm % 44);
        float dd = 0.f, sc = 0.f; int sel = 0;
        if (EP == EP_LOGITS) {
            const float w = v1[gm];
            sel = (w > 0.7f) ? 0 : ((w >= 0.3f) ? 1 : 2);
            dd = v2[gm];
            sc = scale_ptr[0];
        }
        float* crow = Cb + (long long)rr * ldc;
        #pragma unroll
        for (int p = 0; p < 4; p++) {
            const int gn0 = n0 + ((p < 2) ? (tx * 4 + p * 2) : (64 + tx * 4 + (p - 2) * 2));
            const uint2 u = *reinterpret_cast<const uint2*>(&acc[i][p]);
            #pragma unroll
            for (int h = 0; h < 2; h++) {
                const int gn = gn0 + h;
                if (GUARD && gn >= N) continue;
                float v = __uint_as_float(h ? u.y : u.x);
                if (EP == EP_BIAS) {
                    v += v1[z * biasStride + gn];
                } else if (EP == EP_BIAS_GELU) {
                    v = gelu_exact(v + v1[z * biasStride + gn]);
                } else if (EP == EP_LOGITS) {
                    v = ((gn / PS) == sel) ? sc * (v + dd) : 0.f;
                }
                crow[gn] = v;
            }
        }
    }
}

// ---------------- mu rearrange: mu_cat[d*132 + e*44+s] = mu[e,d,s] ----------------
__global__ void k_prep_mu(const float* __restrict__ mu, float* __restrict__ mu_cat) {
    int idx = blockIdx.x * blockDim.x + threadIdx.x;
    if (idx >= PD * PES) return;
    int d = idx / PES, j = idx % PES;
    int e = j / PS, s = j % PS;
    mu_cat[idx] = mu[((long long)e * PD + d) * PMAXS + s];
}

// ---------------- slot_input = [cls, mean(attn)] ----------------
__global__ void k_build_slotinput(const float* __restrict__ x,
                                  const float* __restrict__ attn,
                                  float* __restrict__ si) {
    int b = blockIdx.x;
    int t = threadIdx.x;
    __shared__ float red[8];
    float s = (t < PN) ? attn[b * PN + t] : 0.f;
    for (int o = 16; o; o >>= 1) s += __shfl_xor_sync(~0u, s, o);
    if ((t & 31) == 0) red[t >> 5] = s;
    __syncthreads();
    const float* cls = x + (long long)b * 129 * PD;
    float* o = si + (long long)b * 769;
    for (int d = t; d < PD; d += 256) o[d] = cls[d];
    if (t == 0) {
        float m = 0.f;
        #pragma unroll
        for (int i = 0; i < 8; i++) m += red[i];
        o[PD] = m * (1.f / (float)PN);
    }
}

// ---------------- LayerNorm + dot ----------------
__global__ void k_ln_dot(const float* __restrict__ x,
                         const float* __restrict__ gamma,
                         const float* __restrict__ beta,
                         const float* __restrict__ slot_bias,
                         float* __restrict__ img_n,
                         float* __restrict__ dot) {
    const int m = blockIdx.x;
    const int b = m >> 7;
    const int n = m & 127;
    const float* row = x + ((long long)b * 129 + 1 + n) * PD;
    const int t = threadIdx.x;
    const int w = t >> 5, l = t & 31;
    __shared__ float rs[8], rq[8];

    float v[3], s = 0.f, sq = 0.f;
    #pragma unroll
    for (int i = 0; i < 3; i++) {
        v[i] = row[t + i * 256];
        s += v[i];
        sq += v[i] * v[i];
    }
    for (int o = 16; o; o >>= 1) {
        s  += __shfl_xor_sync(~0u, s, o);
        sq += __shfl_xor_sync(~0u, sq, o);
    }
    if (l == 0) { rs[w] = s; rq[w] = sq; }
    __syncthreads();
    float ts = 0.f, tq = 0.f;
    #pragma unroll
    for (int i = 0; i < 8; i++) { ts += rs[i]; tq += rq[i]; }
    const float mean = ts * (1.f / (float)PD);
    const float var  = tq * (1.f / (float)PD) - mean * mean;
    const float inv  = rsqrtf(var + 1e-5f);
    __syncthreads();

    const float* sb = slot_bias + (long long)b * PD;
    float* orow = img_n + (long long)m * PD;
    float dp = 0.f;
    #pragma unroll
    for (int i = 0; i < 3; i++) {
        const int d = t + i * 256;
        const float y = (v[i] - mean) * inv * gamma[d] + beta[d];
        orow[d] = y;
        dp += y * sb[d];
    }
    for (int o = 16; o; o >>= 1) dp += __shfl_xor_sync(~0u, dp, o);
    if (l == 0) rs[w] = dp;
    __syncthreads();
    if (t == 0) {
        float d2 = 0.f;
        #pragma unroll
        for (int i = 0; i < 8; i++) d2 += rs[i];
        dot[m] = d2;
    }
}

// ---------------- dispatch softmax (over tokens) ----------------
__global__ void k_dispatch(const float* __restrict__ logits, float* __restrict__ disp) {
    const int be = blockIdx.x;
    const int b = be / PE, e = be % PE;
    __shared__ float tile[PN][PS];
    __shared__ float csum[PS];
    const int t = threadIdx.x;
    const float* base = logits + (long long)b * PN * PES + e * PS;
    for (int idx = t; idx < PN * PS; idx += 256) {
        const int n = idx / PS, j = idx % PS;
        tile[n][j] = base[(long long)n * PES + j];
    }
    __syncthreads();
    if (t < PS) {
        float mx = -1e30f;
        for (int n = 0; n < PN; n++) mx = fmaxf(mx, tile[n][t]);
        float sm = 0.f;
        for (int n = 0; n < PN; n++) {
            const float ev = expf(tile[n][t] - mx);
            tile[n][t] = ev;
            sm += ev;
        }
        csum[t] = sm;
    }
    __syncthreads();
    float* ob = disp + (long long)b * PN * PES + e * PS;
    for (int idx = t; idx < PN * PS; idx += 256) {
        const int n = idx / PS, j = idx % PS;
        ob[(long long)n * PES + j] = tile[n][j] / csum[j];
    }
}

// ---------------- combine softmax (over 132 slots) ----------------
__global__ void k_combine(const float* __restrict__ logits, float* __restrict__ comb) {
    const int row = blockIdx.x * 8 + (threadIdx.x >> 5);
    const int l = threadIdx.x & 31;
    if (row >= PM_TOK) return;
    const float* r = logits + (long long)row * PES;
    float vals[5], mx = -1e30f;
    #pragma unroll
    for (int i = 0; i < 5; i++) {
        const int j = l + i * 32;
        vals[i] = (j < PES) ? r[j] : -1e30f;
        mx = fmaxf(mx, vals[i]);
    }
    for (int o = 16; o; o >>= 1) mx = fmaxf(mx, __shfl_xor_sync(~0u, mx, o));
    float s = 0.f;
    #pragma unroll
    for (int i = 0; i < 5; i++) {
        const int j = l + i * 32;
        if (j < PES) { vals[i] = expf(vals[i] - mx); s += vals[i]; }
    }
    for (int o = 16; o; o >>= 1) s += __shfl_xor_sync(~0u, s, o);
    const float inv = 1.f / s;
    float* o = comb + (long long)row * PES;
    #pragma unroll
    for (int i = 0; i < 5; i++) {
        const int j = l + i * 32;
        if (j < PES) o[j] = vals[i] * inv;
    }
}

// ---------------- launch ----------------
extern "C" void kernel_launch(void* const* d_in, const int* in_sizes, int n_in,
                              void* d_out, int out_size) {
    const float* x      = (const float*)d_in[0];
    const float* attn   = (const float*)d_in[1];
    const float* gamma  = (const float*)d_in[2];
    const float* beta   = (const float*)d_in[3];
    const float* vsg_w  = (const float*)d_in[4];
    const float* vsg_b  = (const float*)d_in[5];
    const float* mu     = (const float*)d_in[6];
    const float* scale  = (const float*)d_in[7];
    const float* w1     = (const float*)d_in[8];
    const float* b1     = (const float*)d_in[9];
    const float* w2     = (const float*)d_in[10];
    const float* b2     = (const float*)d_in[11];
    const float* cw1    = (const float*)d_in[12];
    const float* cb1    = (const float*)d_in[13];
    const float* cw2    = (const float*)d_in[14];
    const float* cb2    = (const float*)d_in[15];
    float* out = (float*)d_out;

    float *p_si, *p_sb, *p_imgn, *p_dot, *p_mu, *p_log, *p_disp, *p_comb;
    float *p_sin, *p_h, *p_sout, *p_clsh;
    cudaGetSymbolAddress((void**)&p_si,   g_slot_input);
    cudaGetSymbolAddress((void**)&p_sb,   g_slot_bias);
    cudaGetSymbolAddress((void**)&p_imgn, g_img_n);
    cudaGetSymbolAddress((void**)&p_dot,  g_dot);
    cudaGetSymbolAddress((void**)&p_mu,   g_mu_cat);
    cudaGetSymbolAddress((void**)&p_log,  g_logits);
    cudaGetSymbolAddress((void**)&p_disp, g_dispatch);
    cudaGetSymbolAddress((void**)&p_comb, g_combine);
    cudaGetSymbolAddress((void**)&p_sin,  g_slot_in);
    cudaGetSymbolAddress((void**)&p_h,    g_hbuf);
    cudaGetSymbolAddress((void**)&p_sout, g_slot_out);
    cudaGetSymbolAddress((void**)&p_clsh, g_cls_h);

    // 1. mu -> (768,132)
    k_prep_mu<<<(PD * PES + 255) / 256, 256>>>(mu, p_mu);
    // 2. slot_input
    k_build_slotinput<<<PB, 256>>>(x, attn, p_si);
    // 3. slot_bias = slot_input @ vsg_w + vsg_b   (256,768,K=769)
    fgemm2<true, false, false, EP_BIAS><<<dim3(2, 6, 1), 256>>>(
        p_si, vsg_w, p_sb, PB, PD, 769, 769, PD, PD,
        0, 0, 0, vsg_b, nullptr, nullptr, 0);
    // 4. LayerNorm + dot
    k_ln_dot<<<PM_TOK, 256>>>(x, gamma, beta, p_sb, p_imgn, p_dot);
    // 5. logits (32768,132,K=768)
    fgemm2<true, false, false, EP_LOGITS><<<dim3(PM_TOK / 128, 2, 1), 256>>>(
        p_imgn, p_mu, p_log, PM_TOK, PES, PD, PD, PES, PES,
        0, 0, 0, attn, p_dot, scale, 0);
    // 6/7. softmaxes
    k_dispatch<<<PB * PE, 256>>>(p_log, p_disp);
    k_combine<<<PM_TOK / 8, 256>>>(p_log, p_comb);
    // 8. slot_in[b] = dispatch[b]^T @ img[b]   (132,768,K=128) batched
    fgemm2<true, true, false, EP_STORE><<<dim3(2, 6, PB), 256>>>(
        p_disp, x + PD, p_sin, PES, PD, PN, PES, PD, PD,
        (long long)PN * PES, (long long)129 * PD, (long long)PES * PD,
        nullptr, nullptr, nullptr, 0);
    // 9. FFN1 (11264,1024,K=768) per expert
    fgemm2<false, false, true, EP_BIAS_GELU><<<dim3(PM_FFN / 128, PH / 128, PE), 256>>>(
        p_sin, w1, p_h, PM_FFN, PH, PD, PD, PH, PH,
        0, (long long)PD * PH, 0, b1, nullptr, nullptr, PH);
    // 10. FFN2 (11264,768,K=1024) per expert
    fgemm2<false, false, true, EP_BIAS><<<dim3(PM_FFN / 128, PD / 128, PE), 256>>>(
        p_h, w2, p_sout, PM_FFN, PD, PH, PH, PD, PD,
        0, (long long)PH * PD, 0, b2, nullptr, nullptr, PD);
    // 11. img_out[b] = combine[b] @ slot_out[b]  (128,768,K=132) batched
    fgemm2<true, false, false, EP_STORE><<<dim3(1, 6, PB), 256>>>(
        p_comb, p_sout, out + PD, PN, PD, PES, PES, PD, PD,
        (long long)PN * PES, (long long)PES * PD, (long long)129 * PD,
        nullptr, nullptr, nullptr, 0);
    // 12. cls1 (256,3072,K=768)
    fgemm2<false, false, false, EP_BIAS_GELU><<<dim3(2, 24, 1), 256>>>(
        x, cw1, p_clsh, PB, 4 * PD, PD, 129 * PD, 4 * PD, 4 * PD,
        0, 0, 0, cb1, nullptr, nullptr, 0);
    // 13. cls2 (256,768,K=3072) -> out row 0
    fgemm2<false, false, false, EP_BIAS><<<dim3(2, 6, 1), 256>>>(
        p_clsh, cw2, out, PB, PD, 4 * PD, 4 * PD, PD, 129 * PD,
        0, 0, 0, cb2, nullptr, nullptr, 0);
}